// round 2
// baseline (speedup 1.0000x reference)
#include <cuda_runtime.h>

// Problem constants
#define BB   1024
#define TT   512
#define II   100
#define HH   150
#define HP   160    // padded hidden (mult of 32)
#define OO   3
#define WP   161    // weight smem pitch (conflict-free transpose fill)

// Output tuple layout: out, hidden, logits
#define HID_OFF  ((size_t)BB * TT * OO)
#define LOG_OFF  (HID_OFF + (size_t)BB * TT * HH)

typedef unsigned long long u64t;

// Scratch: input projection xw[bt][HP] (~335 MB)
__device__ float g_xw[(size_t)BB * TT * HP];

// ---- f32x2 packed helpers (sm_103a FFMA2 path) ------------------------------
__device__ __forceinline__ u64t pk2(float lo, float hi) {
    u64t r; asm("mov.b64 %0, {%1,%2};" : "=l"(r) : "f"(lo), "f"(hi)); return r;
}
__device__ __forceinline__ void upk2(u64t v, float& lo, float& hi) {
    asm("mov.b64 {%0,%1}, %2;" : "=f"(lo), "=f"(hi) : "l"(v));
}
__device__ __forceinline__ u64t fma2(u64t a, u64t b, u64t c) {
    u64t d; asm("fma.rn.f32x2 %0, %1, %2, %3;" : "=l"(d) : "l"(a), "l"(b), "l"(c)); return d;
}

// ---------------------------------------------------------------------------
// Kernel 1: xw = x @ W_ih^T.  32-row tiles, 320 threads (j=tid%160, half),
// x staged row-pair-packed so inner loop is pure FFMA2.
// ---------------------------------------------------------------------------
__global__ void __launch_bounds__(320) xw_kernel(const float* __restrict__ x,
                                                 const float* __restrict__ W_ih) {
    extern __shared__ float sm[];
    float* WihT = sm;                         // [II][WP]
    u64t*  xsp  = (u64t*)(sm + II * WP + 12); // [16 rpairs][II] packed; +12 floats keeps 16B align (16100+12=16112, 16112*4%16==0)
    const int tid = threadIdx.x;

    for (int i = tid; i < II * WP; i += 320) WihT[i] = 0.f;
    __syncthreads();
    for (int idx = tid; idx < HH * II; idx += 320) {
        int h = idx / II, i = idx - h * II;
        WihT[i * WP + h] = W_ih[idx];
    }

    const int j = tid % HP;
    const int half = tid / HP;
    const int nTiles = (BB * TT) / 32;

    for (int tile = blockIdx.x; tile < nTiles; tile += gridDim.x) {
        const int bt0 = tile * 32;
        __syncthreads();   // also covers the first-iteration weight fill
        float* xspf = (float*)xsp;
        for (int idx = tid; idx < 32 * II; idx += 320) {
            int row = idx / II, i = idx - row * II;
            xspf[(row >> 1) * (2 * II) + 2 * i + (row & 1)] = x[(size_t)bt0 * II + idx];
        }
        __syncthreads();

        u64t acc[8];
#pragma unroll
        for (int rp = 0; rp < 8; rp++) acc[rp] = 0ull;

#pragma unroll 5
        for (int k2 = 0; k2 < II / 2; k2++) {
            const float w0 = WihT[(2 * k2 + 0) * WP + j];
            const float w1 = WihT[(2 * k2 + 1) * WP + j];
            const u64t W0 = pk2(w0, w0);
            const u64t W1 = pk2(w1, w1);
#pragma unroll
            for (int rp = 0; rp < 8; rp++) {
                ulonglong2 xv = *(const ulonglong2*)(xsp + (size_t)(half * 8 + rp) * II + 2 * k2);
                acc[rp] = fma2(xv.x, W0, acc[rp]);
                acc[rp] = fma2(xv.y, W1, acc[rp]);
            }
        }
#pragma unroll
        for (int rp = 0; rp < 8; rp++) {
            float lo, hi; upk2(acc[rp], lo, hi);
            int r0 = bt0 + half * 16 + 2 * rp;
            g_xw[(size_t)r0 * HP + j]       = lo;
            g_xw[(size_t)(r0 + 1) * HP + j] = hi;
        }
    }
}

// ---------------------------------------------------------------------------
// Kernel 2: sequential RNN. 128 CTAs x 8 batch rows, 160 threads (R=8/thread).
// h state kept row-pair-packed in smem; inner loop = 2 LDS.32 + 4 LDS.128 +
// 8 FFMA2 per 2 k. One barrier per step.
// ---------------------------------------------------------------------------
__global__ void __launch_bounds__(160) rnn_kernel(const float* __restrict__ h0,
                                                  const float* __restrict__ W_hh,
                                                  float* __restrict__ out) {
    extern __shared__ float sm[];
    float* WhhT = sm;                       // [HP][WP] zero-padded
    u64t*  hsp  = (u64t*)(sm + HP * WP);    // [2][4 rpairs][HP] packed (HP*WP=25760, *4 %16==0)
    const int tid = threadIdx.x;
    const int b0 = blockIdx.x * 8;
    const int j = tid;

    for (int i = tid; i < HP * WP; i += 160) WhhT[i] = 0.f;
    __syncthreads();
    for (int idx = tid; idx < HH * HH; idx += 160) {
        int jj = idx / HH, kk = idx - jj * HH;
        WhhT[kk * WP + jj] = W_hh[idx];     // WhhT[k][j]
    }
    for (int idx = tid; idx < 4 * HP; idx += 160) {
        int rp = idx / HP, k = idx - rp * HP;
        float lo = (k < HH) ? h0[(b0 + 2 * rp) * HH + k] : 0.f;
        float hi = (k < HH) ? h0[(b0 + 2 * rp + 1) * HH + k] : 0.f;
        hsp[(size_t)rp * HP + k] = pk2(lo, hi);
    }
    __syncthreads();

    float* hid_out = out + HID_OFF;
    int cur = 0;

    for (int t = 0; t < TT; t++) {
        // accumulators start at xw (issue gmem loads first; latency hidden)
        u64t acc[4];
#pragma unroll
        for (int rp = 0; rp < 4; rp++) {
            float lo = g_xw[((size_t)(b0 + 2 * rp) * TT + t) * HP + j];
            float hi = g_xw[((size_t)(b0 + 2 * rp + 1) * TT + t) * HP + j];
            acc[rp] = pk2(lo, hi);
        }

        const u64t* hcur = hsp + (size_t)cur * (4 * HP);
#pragma unroll 8
        for (int k2 = 0; k2 < HP / 2; k2++) {
            const float w0 = WhhT[(2 * k2 + 0) * WP + j];
            const float w1 = WhhT[(2 * k2 + 1) * WP + j];
            const u64t W0 = pk2(w0, w0);
            const u64t W1 = pk2(w1, w1);
#pragma unroll
            for (int rp = 0; rp < 4; rp++) {
                ulonglong2 hv = *(const ulonglong2*)(hcur + (size_t)rp * HP + 2 * k2);
                acc[rp] = fma2(hv.x, W0, acc[rp]);
                acc[rp] = fma2(hv.y, W1, acc[rp]);
            }
        }

        const int nxt = cur ^ 1;
        u64t* hnxt = hsp + (size_t)nxt * (4 * HP);
#pragma unroll
        for (int rp = 0; rp < 4; rp++) {
            float lo, hi; upk2(acc[rp], lo, hi);
            lo = fmaxf(lo, 0.f);
            hi = fmaxf(hi, 0.f);
            hnxt[(size_t)rp * HP + j] = pk2(lo, hi);
            if (j < HH) {
                hid_out[((size_t)(b0 + 2 * rp) * TT + t) * HH + j]     = lo;
                hid_out[((size_t)(b0 + 2 * rp + 1) * TT + t) * HH + j] = hi;
            }
        }
        __syncthreads();
        cur = nxt;
    }
}

// ---------------------------------------------------------------------------
// Kernel 3: logits = hidden @ W_fc^T; out = one_hot(argmax(logits+g)).
// ---------------------------------------------------------------------------
__global__ void __launch_bounds__(256) post_kernel(const float* __restrict__ g,
                                                   const float* __restrict__ W_fc,
                                                   float* __restrict__ out) {
    __shared__ float wfc[OO * HP];
    const int tid = threadIdx.x;
    for (int i = tid; i < OO * HP; i += 256) {
        int o = i / HP, k = i - o * HP;
        wfc[i] = (k < HH) ? W_fc[o * HH + k] : 0.f;
    }
    __syncthreads();

    const int warp = tid >> 5, lane = tid & 31;
    const size_t bt = (size_t)blockIdx.x * 8 + warp;
    const float* hid = out + HID_OFF + bt * HH;

    float hv[5];
#pragma unroll
    for (int m = 0; m < 5; m++) {
        int k = lane + 32 * m;
        hv[m] = (k < HH) ? hid[k] : 0.f;
    }
    float p[OO];
#pragma unroll
    for (int o = 0; o < OO; o++) {
        float s = 0.f;
#pragma unroll
        for (int m = 0; m < 5; m++)
            s = fmaf(hv[m], wfc[o * HP + lane + 32 * m], s);
#pragma unroll
        for (int off = 16; off > 0; off >>= 1)
            s += __shfl_xor_sync(0xffffffffu, s, off);
        p[o] = s;
    }
    if (lane == 0) {
        const float z0 = p[0] + g[bt * OO + 0];
        const float z1 = p[1] + g[bt * OO + 1];
        const float z2 = p[2] + g[bt * OO + 2];
        int idx = 0; float best = z0;
        if (z1 > best) { best = z1; idx = 1; }
        if (z2 > best) { best = z2; idx = 2; }
        float* op = out + bt * OO;
        op[0] = (idx == 0) ? 1.f : 0.f;
        op[1] = (idx == 1) ? 1.f : 0.f;
        op[2] = (idx == 2) ? 1.f : 0.f;
        float* lp = out + LOG_OFF + bt * OO;
        lp[0] = p[0]; lp[1] = p[1]; lp[2] = p[2];
    }
}

// ---------------------------------------------------------------------------
extern "C" void kernel_launch(void* const* d_in, const int* in_sizes, int n_in,
                              void* d_out, int out_size) {
    const float* x    = (const float*)d_in[0];
    const float* h0   = (const float*)d_in[1];
    const float* g    = (const float*)d_in[2];
    const float* W_ih = (const float*)d_in[3];
    const float* W_hh = (const float*)d_in[4];
    const float* W_fc = (const float*)d_in[5];
    float* out = (float*)d_out;

    const int xw_smem  = (II * WP + 12) * (int)sizeof(float) + 16 * II * (int)sizeof(u64t); // ~77.3 KB
    const int rnn_smem = HP * WP * (int)sizeof(float) + 2 * 4 * HP * (int)sizeof(u64t);     // ~113.3 KB
    cudaFuncSetAttribute(xw_kernel,  cudaFuncAttributeMaxDynamicSharedMemorySize, xw_smem);
    cudaFuncSetAttribute(rnn_kernel, cudaFuncAttributeMaxDynamicSharedMemorySize, rnn_smem);

    xw_kernel<<<2048, 320, xw_smem>>>(x, W_ih);
    rnn_kernel<<<BB / 8, 160, rnn_smem>>>(h0, W_hh, out);
    post_kernel<<<(BB * TT) / 8, 256>>>(g, W_fc, out);
}

// round 3
// speedup vs baseline: 1.5305x; 1.5305x over previous
#include <cuda_runtime.h>

// Problem constants
#define BB   1024
#define TT   512
#define II   100
#define HH   150
#define HP   160    // padded hidden for g_xw rows (mult of 32)
#define OO   3
#define WP   161    // xw weight smem pitch

// rnn kernel geometry
#define K4   152    // padded K (4 chunks of 38)
#define KC   38     // k-chunk per quarter
#define HROW 12     // hs row stride in floats (16B-aligned float4 pairs, low conflict)

// Output tuple layout: out, hidden, logits
#define HID_OFF  ((size_t)BB * TT * OO)
#define LOG_OFF  (HID_OFF + (size_t)BB * TT * HH)

// Scratch: input projection xw[bt][HP] (~335 MB)
__device__ float g_xw[(size_t)BB * TT * HP];

// ---------------------------------------------------------------------------
// Kernel 1: xw[bt][j] = sum_i x[bt][i] * W_ih[j][i]  (R1 version: best known)
// 320 threads: j = tid%160, half = tid/160, 8 bt-rows per thread.
// ---------------------------------------------------------------------------
__global__ void __launch_bounds__(320) xw_kernel(const float* __restrict__ x,
                                                 const float* __restrict__ W_ih) {
    extern __shared__ float sm[];
    float* WihT = sm;                 // [II][WP]
    float* xs   = sm + II * WP;       // [16][II]
    const int tid = threadIdx.x;

    for (int i = tid; i < II * WP; i += 320) WihT[i] = 0.f;
    __syncthreads();
    for (int idx = tid; idx < HH * II; idx += 320) {
        int h = idx / II, i = idx - h * II;
        WihT[i * WP + h] = W_ih[idx];
    }

    const int j = tid % HP;
    const int half = tid / HP;
    const int nTiles = (BB * TT) / 16;

    for (int tile = blockIdx.x; tile < nTiles; tile += gridDim.x) {
        const int bt0 = tile * 16;
        __syncthreads();
        for (int i2 = tid; i2 < 16 * II; i2 += 320)
            xs[i2] = x[(size_t)bt0 * II + i2];
        __syncthreads();

        float acc[8] = {0.f, 0.f, 0.f, 0.f, 0.f, 0.f, 0.f, 0.f};
        const float* xrow = xs + half * 8 * II;
#pragma unroll
        for (int kq = 0; kq < II / 4; kq++) {
            const float w0 = WihT[(4 * kq + 0) * WP + j];
            const float w1 = WihT[(4 * kq + 1) * WP + j];
            const float w2 = WihT[(4 * kq + 2) * WP + j];
            const float w3 = WihT[(4 * kq + 3) * WP + j];
#pragma unroll
            for (int r = 0; r < 8; r++) {
                float4 xv = *(const float4*)&xrow[r * II + 4 * kq];
                acc[r] = fmaf(xv.x, w0, acc[r]);
                acc[r] = fmaf(xv.y, w1, acc[r]);
                acc[r] = fmaf(xv.z, w2, acc[r]);
                acc[r] = fmaf(xv.w, w3, acc[r]);
            }
        }
#pragma unroll
        for (int r = 0; r < 8; r++)
            g_xw[(size_t)(bt0 + half * 8 + r) * HP + j] = acc[r];
    }
}

// ---------------------------------------------------------------------------
// Kernel 2: sequential RNN. 128 CTAs x 8 batch rows, 640 threads (20 warps,
// perfect 5/5/5/5 SMSP balance). Thread = (j, kc): holds W_hh[j][38kc..+37]
// in REGISTERS for all 512 steps. h stored transposed hs[k][row] so one
// broadcast LDS.128 feeds 4 rows. Cross-kc reduction via smem psum.
// Inner loop per step per warp: 76 LDS wf + 304 FFMA -> fma-pipe bound.
// ---------------------------------------------------------------------------
__global__ void __launch_bounds__(640, 1) rnn_kernel(const float* __restrict__ h0,
                                                     const float* __restrict__ W_hh,
                                                     float* __restrict__ out) {
    __shared__ __align__(16) float hs[2][K4 * HROW];   // [buf][k][row], rows 8..11 pad
    __shared__ float psum[4 * 8 * HP];                  // [kc][row][j]

    const int tid = threadIdx.x;
    const int j   = tid % HP;    // output neuron
    const int kc  = tid / HP;    // k-chunk quarter
    const int b0  = blockIdx.x * 8;

    // --- one-time: weights into registers ---
    float w[KC];
#pragma unroll
    for (int i = 0; i < KC; i++) {
        int k = KC * kc + i;
        w[i] = (j < HH && k < HH) ? W_hh[j * HH + k] : 0.f;
    }

    // --- init hs: zero both buffers, then fill h0 (transposed) ---
    for (int idx = tid; idx < 2 * K4 * HROW; idx += 640) ((float*)hs)[idx] = 0.f;
    __syncthreads();
    for (int idx = tid; idx < HH * 8; idx += 640) {
        int k = idx >> 3, r = idx & 7;
        hs[0][k * HROW + r] = h0[(b0 + r) * HH + k];
    }
    __syncthreads();

    // xw pointers for this thread's two reduction rows (r0=2kc, r1=2kc+1)
    const int r0 = 2 * kc, r1 = 2 * kc + 1;
    const float* px0 = g_xw + (size_t)(b0 + r0) * TT * HP + j;
    const float* px1 = g_xw + (size_t)(b0 + r1) * TT * HP + j;
    float xw0 = px0[0];
    float xw1 = px1[0];

    float* hid_out = out + HID_OFF;
    int cur = 0;

    for (int t = 0; t < TT; t++) {
        // prefetch next step's xw early (latency hidden by FMA loop)
        float nx0 = 0.f, nx1 = 0.f;
        if (t + 1 < TT) { nx0 = px0[HP]; nx1 = px1[HP]; }

        // --- main FMA loop: 8 rows x 38 k, weights in regs, h broadcast ---
        const float* hc = &hs[cur][(KC * kc) * HROW];
        float a0 = 0.f, a1 = 0.f, a2 = 0.f, a3 = 0.f;
        float a4 = 0.f, a5 = 0.f, a6 = 0.f, a7 = 0.f;
#pragma unroll
        for (int i = 0; i < KC; i++) {
            float4 va = *(const float4*)(hc + i * HROW);
            float4 vb = *(const float4*)(hc + i * HROW + 4);
            a0 = fmaf(w[i], va.x, a0);
            a1 = fmaf(w[i], va.y, a1);
            a2 = fmaf(w[i], va.z, a2);
            a3 = fmaf(w[i], va.w, a3);
            a4 = fmaf(w[i], vb.x, a4);
            a5 = fmaf(w[i], vb.y, a5);
            a6 = fmaf(w[i], vb.z, a6);
            a7 = fmaf(w[i], vb.w, a7);
        }

        // --- write partials ---
        float* ps = psum + kc * (8 * HP) + j;
        ps[0 * HP] = a0; ps[1 * HP] = a1; ps[2 * HP] = a2; ps[3 * HP] = a3;
        ps[4 * HP] = a4; ps[5 * HP] = a5; ps[6 * HP] = a6; ps[7 * HP] = a7;
        __syncthreads();

        // --- reduce rows r0, r1 across the 4 kc partials + xw, relu ---
        float s0 = psum[0 * (8 * HP) + r0 * HP + j] + psum[1 * (8 * HP) + r0 * HP + j]
                 + psum[2 * (8 * HP) + r0 * HP + j] + psum[3 * (8 * HP) + r0 * HP + j] + xw0;
        float s1 = psum[0 * (8 * HP) + r1 * HP + j] + psum[1 * (8 * HP) + r1 * HP + j]
                 + psum[2 * (8 * HP) + r1 * HP + j] + psum[3 * (8 * HP) + r1 * HP + j] + xw1;
        s0 = fmaxf(s0, 0.f);
        s1 = fmaxf(s1, 0.f);

        // --- write next h state (transposed) + hidden output ---
        float* hn = hs[cur ^ 1];
        if (j < K4) {
            hn[j * HROW + r0] = (j < HH) ? s0 : 0.f;
            hn[j * HROW + r1] = (j < HH) ? s1 : 0.f;
        }
        if (j < HH) {
            hid_out[((size_t)(b0 + r0) * TT + t) * HH + j] = s0;
            hid_out[((size_t)(b0 + r1) * TT + t) * HH + j] = s1;
        }

        xw0 = nx0; xw1 = nx1;
        px0 += HP; px1 += HP;
        __syncthreads();
        cur ^= 1;
    }
}

// ---------------------------------------------------------------------------
// Kernel 3: logits = hidden @ W_fc^T; out = one_hot(argmax(logits+g)).
// ---------------------------------------------------------------------------
__global__ void __launch_bounds__(256) post_kernel(const float* __restrict__ g,
                                                   const float* __restrict__ W_fc,
                                                   float* __restrict__ out) {
    __shared__ float wfc[OO * HP];
    const int tid = threadIdx.x;
    for (int i = tid; i < OO * HP; i += 256) {
        int o = i / HP, k = i - o * HP;
        wfc[i] = (k < HH) ? W_fc[o * HH + k] : 0.f;
    }
    __syncthreads();

    const int warp = tid >> 5, lane = tid & 31;
    const size_t bt = (size_t)blockIdx.x * 8 + warp;
    const float* hid = out + HID_OFF + bt * HH;

    float hv[5];
#pragma unroll
    for (int m = 0; m < 5; m++) {
        int k = lane + 32 * m;
        hv[m] = (k < HH) ? hid[k] : 0.f;
    }
    float p[OO];
#pragma unroll
    for (int o = 0; o < OO; o++) {
        float s = 0.f;
#pragma unroll
        for (int m = 0; m < 5; m++)
            s = fmaf(hv[m], wfc[o * HP + lane + 32 * m], s);
#pragma unroll
        for (int off = 16; off > 0; off >>= 1)
            s += __shfl_xor_sync(0xffffffffu, s, off);
        p[o] = s;
    }
    if (lane == 0) {
        const float z0 = p[0] + g[bt * OO + 0];
        const float z1 = p[1] + g[bt * OO + 1];
        const float z2 = p[2] + g[bt * OO + 2];
        int idx = 0; float best = z0;
        if (z1 > best) { best = z1; idx = 1; }
        if (z2 > best) { best = z2; idx = 2; }
        float* op = out + bt * OO;
        op[0] = (idx == 0) ? 1.f : 0.f;
        op[1] = (idx == 1) ? 1.f : 0.f;
        op[2] = (idx == 2) ? 1.f : 0.f;
        float* lp = out + LOG_OFF + bt * OO;
        lp[0] = p[0]; lp[1] = p[1]; lp[2] = p[2];
    }
}

// ---------------------------------------------------------------------------
extern "C" void kernel_launch(void* const* d_in, const int* in_sizes, int n_in,
                              void* d_out, int out_size) {
    const float* x    = (const float*)d_in[0];
    const float* h0   = (const float*)d_in[1];
    const float* g    = (const float*)d_in[2];
    const float* W_ih = (const float*)d_in[3];
    const float* W_hh = (const float*)d_in[4];
    const float* W_fc = (const float*)d_in[5];
    float* out = (float*)d_out;

    const int xw_smem = (II * WP + 16 * II) * (int)sizeof(float);   // ~70.8 KB
    cudaFuncSetAttribute(xw_kernel, cudaFuncAttributeMaxDynamicSharedMemorySize, xw_smem);

    xw_kernel<<<2048, 320, xw_smem>>>(x, W_ih);
    rnn_kernel<<<BB / 8, 640>>>(h0, W_hh, out);
    post_kernel<<<(BB * TT) / 8, 256>>>(g, W_fc, out);
}